// round 1
// baseline (speedup 1.0000x reference)
#include <cuda_runtime.h>
#include <cuda_bf16.h>

// Problem constants (from reference): SEQ=4096, BATCH=8, HIDDEN=1024, FEATURES=1024
#define HIDDEN   1024
#define FEATURES 1024
#define M_TOTAL  32768           // SEQ * BATCH
#define LN_EPS   1e-6f

// ---------------------------------------------------------------------------
// Kernel 1: LayerNorm (scale-only affine) over the hidden axis.
// One block per row, 256 threads, 4 floats (float4) per thread.
// Writes ln_output (fp32) which is both an output and the GEMM A operand.
// ---------------------------------------------------------------------------
__global__ void __launch_bounds__(256) ln_kernel(const float* __restrict__ x,
                                                 const float* __restrict__ scale,
                                                 float* __restrict__ ln_out) {
    const int row = blockIdx.x;
    const int t   = threadIdx.x;

    const float4 v = reinterpret_cast<const float4*>(x)[(size_t)row * (HIDDEN / 4) + t];

    float s  = v.x + v.y + v.z + v.w;
    float sq = v.x * v.x + v.y * v.y + v.z * v.z + v.w * v.w;

    #pragma unroll
    for (int o = 16; o > 0; o >>= 1) {
        s  += __shfl_xor_sync(0xFFFFFFFFu, s,  o);
        sq += __shfl_xor_sync(0xFFFFFFFFu, sq, o);
    }

    __shared__ float red[16];
    __shared__ float stats[2];
    const int w = t >> 5, l = t & 31;
    if (l == 0) { red[w] = s; red[w + 8] = sq; }
    __syncthreads();

    if (t < 32) {
        float a = (t < 8) ? red[t]     : 0.0f;
        float b = (t < 8) ? red[t + 8] : 0.0f;
        #pragma unroll
        for (int o = 4; o > 0; o >>= 1) {
            a += __shfl_xor_sync(0xFFFFFFFFu, a, o);
            b += __shfl_xor_sync(0xFFFFFFFFu, b, o);
        }
        if (t == 0) {
            const float mean = a * (1.0f / HIDDEN);
            const float var  = b * (1.0f / HIDDEN) - mean * mean;
            stats[0] = mean;
            stats[1] = rsqrtf(var + LN_EPS);
        }
    }
    __syncthreads();

    const float mean = stats[0];
    const float rstd = stats[1];
    const float4 sc = reinterpret_cast<const float4*>(scale)[t];

    float4 o;
    o.x = (v.x - mean) * rstd * sc.x;
    o.y = (v.y - mean) * rstd * sc.y;
    o.z = (v.z - mean) * rstd * sc.z;
    o.w = (v.w - mean) * rstd * sc.w;
    reinterpret_cast<float4*>(ln_out)[(size_t)row * (HIDDEN / 4) + t] = o;
}

// ---------------------------------------------------------------------------
// Kernel 2: fp32 SGEMM  C[M,N] = A[M,K] @ B[K,N], all row-major.
// 128x128 block tile, BK=8, 256 threads, 8x8 per-thread micro-tile,
// double-buffered shared memory, float4 global loads.
// ---------------------------------------------------------------------------
#define BM 128
#define BN 128
#define BK 8
#define TM 8
#define TN 8

__global__ void __launch_bounds__(256, 2) sgemm_kernel(const float* __restrict__ A,
                                                       const float* __restrict__ B,
                                                       float* __restrict__ C) {
    __shared__ float As[2][BK][BM];   // transposed A tile: As[k][m]
    __shared__ float Bs[2][BK][BN];   // Bs[k][n]

    const int tid = threadIdx.x;

    // Global-load assignments
    const int aRow = tid >> 1;          // 0..127
    const int aCol = (tid & 1) << 2;    // 0 or 4
    const int bRow = tid >> 5;          // 0..7
    const int bCol = (tid & 31) << 2;   // 0..124

    // Compute assignments: 16x16 thread grid of 8x8 micro-tiles
    const int tRow = (tid >> 4) << 3;   // 0..120
    const int tCol = (tid & 15) << 3;   // 0..120

    const float* Aptr = A + ((size_t)(blockIdx.y * BM + aRow)) * HIDDEN + aCol;
    const float* Bptr = B + (size_t)bRow * FEATURES + blockIdx.x * BN + bCol;

    float acc[TM][TN] = {};

    // Prologue: load k-tile 0 into buffer 0
    {
        float4 a4 = *reinterpret_cast<const float4*>(Aptr);
        float4 b4 = *reinterpret_cast<const float4*>(Bptr);
        As[0][aCol + 0][aRow] = a4.x;
        As[0][aCol + 1][aRow] = a4.y;
        As[0][aCol + 2][aRow] = a4.z;
        As[0][aCol + 3][aRow] = a4.w;
        *reinterpret_cast<float4*>(&Bs[0][bRow][bCol]) = b4;
    }
    __syncthreads();

    const int NT = HIDDEN / BK;   // 128 k-tiles
    int buf = 0;

    for (int kt = 0; kt < NT; kt++) {
        float4 an, bn;
        const bool has_next = (kt + 1 < NT);
        if (has_next) {
            an = *reinterpret_cast<const float4*>(Aptr + (kt + 1) * BK);
            bn = *reinterpret_cast<const float4*>(Bptr + (size_t)(kt + 1) * BK * FEATURES);
        }

        #pragma unroll
        for (int k = 0; k < BK; k++) {
            float regM[TM], regN[TN];
            *reinterpret_cast<float4*>(&regM[0]) = *reinterpret_cast<const float4*>(&As[buf][k][tRow]);
            *reinterpret_cast<float4*>(&regM[4]) = *reinterpret_cast<const float4*>(&As[buf][k][tRow + 4]);
            *reinterpret_cast<float4*>(&regN[0]) = *reinterpret_cast<const float4*>(&Bs[buf][k][tCol]);
            *reinterpret_cast<float4*>(&regN[4]) = *reinterpret_cast<const float4*>(&Bs[buf][k][tCol + 4]);
            #pragma unroll
            for (int i = 0; i < TM; i++)
                #pragma unroll
                for (int j = 0; j < TN; j++)
                    acc[i][j] += regM[i] * regN[j];
        }

        if (has_next) {
            const int nb = buf ^ 1;
            As[nb][aCol + 0][aRow] = an.x;
            As[nb][aCol + 1][aRow] = an.y;
            As[nb][aCol + 2][aRow] = an.z;
            As[nb][aCol + 3][aRow] = an.w;
            *reinterpret_cast<float4*>(&Bs[nb][bRow][bCol]) = bn;
        }
        __syncthreads();
        buf ^= 1;
    }

    // Epilogue: vectorized C stores
    float* Cptr = C + ((size_t)(blockIdx.y * BM + tRow)) * FEATURES + blockIdx.x * BN + tCol;
    #pragma unroll
    for (int i = 0; i < TM; i++) {
        float4 o0 = make_float4(acc[i][0], acc[i][1], acc[i][2], acc[i][3]);
        float4 o1 = make_float4(acc[i][4], acc[i][5], acc[i][6], acc[i][7]);
        *reinterpret_cast<float4*>(Cptr + (size_t)i * FEATURES)     = o0;
        *reinterpret_cast<float4*>(Cptr + (size_t)i * FEATURES + 4) = o1;
    }
}

// ---------------------------------------------------------------------------
// Launch: outputs are packed as [z (32768*1024 fp32)] then [ln (32768*1024 fp32)]
// matching the reference's (z, ln_output) tuple flattening.
// ---------------------------------------------------------------------------
extern "C" void kernel_launch(void* const* d_in, const int* in_sizes, int n_in,
                              void* d_out, int out_size) {
    (void)in_sizes; (void)n_in; (void)out_size;
    const float* x     = (const float*)d_in[0];   // [4096, 8, 1024]
    const float* scale = (const float*)d_in[1];   // [1024]
    const float* W     = (const float*)d_in[2];   // [1024, 1024] row-major (H, F)

    float* z  = (float*)d_out;                          // [32768, 1024]
    float* ln = z + (size_t)M_TOTAL * FEATURES;         // [32768, 1024]

    ln_kernel<<<M_TOTAL, 256>>>(x, scale, ln);

    dim3 grid(FEATURES / BN, M_TOTAL / BM);             // (8, 256)
    sgemm_kernel<<<grid, 256>>>(ln, W, z);
}

// round 5
// speedup vs baseline: 2.6811x; 2.6811x over previous
#include <cuda_runtime.h>
#include <cuda_bf16.h>
#include <cstdint>

// Problem: SEQ=4096, BATCH=8, HIDDEN=1024, FEATURES=1024
#define HIDDEN   1024
#define FEATURES 1024
#define M_TOTAL  32768
#define LN_EPS   1e-6f

// 3x-bf16 fp32 emulation: A = [hi | lo | hi], B = [hi ; hi ; lo], K_eff = 3072
#define K_EFF    3072
#define BK       64
#define NSTEPS   (K_EFF / BK)     // 48
#define STAGES   3

#define BM       256
#define BN       128
#define THREADS  256

// smem stage: A[256][64]bf16 (32KB, 128B rows) + B[128][64]bf16 (16KB)
#define A_STAGE_BYTES 32768
#define B_STAGE_BYTES 16384
#define STAGE_BYTES   (A_STAGE_BYTES + B_STAGE_BYTES)   // 48KB
#define SMEM_TOTAL    (STAGES * STAGE_BYTES)            // 144KB

// Scratch (device globals; allocations are forbidden)
__device__ __nv_bfloat16 g_Acat[(size_t)M_TOTAL * 2048];     // [hi | lo]
__device__ __nv_bfloat16 g_Bcat[(size_t)FEATURES * K_EFF];   // [N, 3K] K-major

// ---------------------------------------------------------------------------
// PTX helpers (all sm_80-level: portable to target sm_100)
// ---------------------------------------------------------------------------
__device__ __forceinline__ uint32_t smem_u32(const void* p) {
    return (uint32_t)__cvta_generic_to_shared(p);
}
__device__ __forceinline__ void cp_async16(uint32_t dst, const void* src) {
    asm volatile("cp.async.cg.shared.global [%0], [%1], 16;" :: "r"(dst), "l"(src));
}
__device__ __forceinline__ void cp_commit() {
    asm volatile("cp.async.commit_group;" ::: "memory");
}
__device__ __forceinline__ void cp_wait2() {
    asm volatile("cp.async.wait_group 2;" ::: "memory");
}
__device__ __forceinline__ void ldmatrix_x4(uint32_t& r0, uint32_t& r1,
                                            uint32_t& r2, uint32_t& r3, uint32_t addr) {
    asm volatile("ldmatrix.sync.aligned.m8n8.x4.shared.b16 {%0,%1,%2,%3}, [%4];"
                 : "=r"(r0), "=r"(r1), "=r"(r2), "=r"(r3) : "r"(addr));
}
__device__ __forceinline__ void mma_16816(float& c0, float& c1, float& c2, float& c3,
                                          uint32_t a0, uint32_t a1, uint32_t a2, uint32_t a3,
                                          uint32_t b0, uint32_t b1) {
    asm volatile(
        "mma.sync.aligned.m16n8k16.row.col.f32.bf16.bf16.f32 "
        "{%0,%1,%2,%3}, {%4,%5,%6,%7}, {%8,%9}, {%0,%1,%2,%3};"
        : "+f"(c0), "+f"(c1), "+f"(c2), "+f"(c3)
        : "r"(a0), "r"(a1), "r"(a2), "r"(a3), "r"(b0), "r"(b1));
}
__device__ __forceinline__ uint32_t sw128(uint32_t off) {
    return off ^ ((off >> 3) & 0x70);
}

// ---------------------------------------------------------------------------
// Kernel 1: LayerNorm -> ln fp32 output + A_cat bf16 hi/lo scratch
// ---------------------------------------------------------------------------
__global__ void __launch_bounds__(256) ln_kernel(const float* __restrict__ x,
                                                 const float* __restrict__ scale,
                                                 float* __restrict__ ln_out) {
    const int row = blockIdx.x;
    const int t   = threadIdx.x;

    const float4 v = reinterpret_cast<const float4*>(x)[(size_t)row * (HIDDEN / 4) + t];

    float s  = v.x + v.y + v.z + v.w;
    float sq = v.x * v.x + v.y * v.y + v.z * v.z + v.w * v.w;

    #pragma unroll
    for (int o = 16; o > 0; o >>= 1) {
        s  += __shfl_xor_sync(0xFFFFFFFFu, s,  o);
        sq += __shfl_xor_sync(0xFFFFFFFFu, sq, o);
    }

    __shared__ float red[16];
    __shared__ float stats[2];
    const int w = t >> 5, l = t & 31;
    if (l == 0) { red[w] = s; red[w + 8] = sq; }
    __syncthreads();

    if (t < 32) {
        float a = (t < 8) ? red[t]     : 0.0f;
        float b = (t < 8) ? red[t + 8] : 0.0f;
        #pragma unroll
        for (int o = 4; o > 0; o >>= 1) {
            a += __shfl_xor_sync(0xFFFFFFFFu, a, o);
            b += __shfl_xor_sync(0xFFFFFFFFu, b, o);
        }
        if (t == 0) {
            const float mean = a * (1.0f / HIDDEN);
            const float var  = b * (1.0f / HIDDEN) - mean * mean;
            stats[0] = mean;
            stats[1] = rsqrtf(var + LN_EPS);
        }
    }
    __syncthreads();

    const float mean = stats[0];
    const float rstd = stats[1];
    const float4 sc = reinterpret_cast<const float4*>(scale)[t];

    float o0 = (v.x - mean) * rstd * sc.x;
    float o1 = (v.y - mean) * rstd * sc.y;
    float o2 = (v.z - mean) * rstd * sc.z;
    float o3 = (v.w - mean) * rstd * sc.w;

    reinterpret_cast<float4*>(ln_out)[(size_t)row * (HIDDEN / 4) + t] =
        make_float4(o0, o1, o2, o3);

    __nv_bfloat16 h0 = __float2bfloat16_rn(o0);
    __nv_bfloat16 h1 = __float2bfloat16_rn(o1);
    __nv_bfloat16 h2 = __float2bfloat16_rn(o2);
    __nv_bfloat16 h3 = __float2bfloat16_rn(o3);
    __nv_bfloat16 l0 = __float2bfloat16_rn(o0 - __bfloat162float(h0));
    __nv_bfloat16 l1 = __float2bfloat16_rn(o1 - __bfloat162float(h1));
    __nv_bfloat16 l2 = __float2bfloat16_rn(o2 - __bfloat162float(h2));
    __nv_bfloat16 l3 = __float2bfloat16_rn(o3 - __bfloat162float(h3));

    uint2 uh, ul;
    uh.x = (uint32_t)__bfloat16_as_ushort(h0) | ((uint32_t)__bfloat16_as_ushort(h1) << 16);
    uh.y = (uint32_t)__bfloat16_as_ushort(h2) | ((uint32_t)__bfloat16_as_ushort(h3) << 16);
    ul.x = (uint32_t)__bfloat16_as_ushort(l0) | ((uint32_t)__bfloat16_as_ushort(l1) << 16);
    ul.y = (uint32_t)__bfloat16_as_ushort(l2) | ((uint32_t)__bfloat16_as_ushort(l3) << 16);

    __nv_bfloat16* arow = g_Acat + (size_t)row * 2048;
    *reinterpret_cast<uint2*>(arow + t * 4)        = uh;   // hi cols [0,1024)
    *reinterpret_cast<uint2*>(arow + 1024 + t * 4) = ul;   // lo cols [1024,2048)
}

// ---------------------------------------------------------------------------
// Kernel 2: pack W [K,N] fp32 -> B_cat [N, 3072] bf16 K-major
// ---------------------------------------------------------------------------
__global__ void __launch_bounds__(256) pack_b_kernel(const float* __restrict__ W) {
    __shared__ float tile[32][33];
    const int k0 = blockIdx.x * 32;
    const int n0 = blockIdx.y * 32;
    const int tx = threadIdx.x;
    const int ty = threadIdx.y;

    #pragma unroll
    for (int r = 0; r < 4; r++)
        tile[ty + r * 8][tx] = W[(size_t)(k0 + ty + r * 8) * FEATURES + n0 + tx];
    __syncthreads();

    #pragma unroll
    for (int r = 0; r < 4; r++) {
        const int n = n0 + ty + r * 8;
        const int k = k0 + tx;
        const float v = tile[tx][ty + r * 8];
        __nv_bfloat16 h  = __float2bfloat16_rn(v);
        __nv_bfloat16 lo = __float2bfloat16_rn(v - __bfloat162float(h));
        __nv_bfloat16* brow = g_Bcat + (size_t)n * K_EFF;
        brow[k]        = h;
        brow[1024 + k] = h;
        brow[2048 + k] = lo;
    }
}

// ---------------------------------------------------------------------------
// Kernel 3: bf16 mma.sync GEMM, 256x128 CTA tile, K_eff=3072, 3-stage cp.async
// 8 warps in 4(M) x 2(N); warptile 64x64; HMMA m16n8k16.
// ---------------------------------------------------------------------------
__device__ __forceinline__ void load_stage(uint32_t sbase, int kt, int m0, int n0, int t) {
    const int acol = (kt < 32 ? kt : kt - 32) * BK;   // hi, lo, hi
    const int bcol = kt * BK;
    const int tr = t >> 3;       // 0..31
    const int j  = t & 7;        // 16B chunk in 128B row
    const uint32_t coff = j * 16;

    #pragma unroll
    for (int i = 0; i < 8; i++) {                     // A: 256 rows
        const int row = i * 32 + tr;
        const uint32_t sw = sw128((uint32_t)row * 128 + coff);
        cp_async16(sbase + sw, g_Acat + (size_t)(m0 + row) * 2048 + acol + j * 8);
    }
    #pragma unroll
    for (int i = 0; i < 4; i++) {                     // B: 128 rows
        const int row = i * 32 + tr;
        const uint32_t sw = sw128((uint32_t)row * 128 + coff);
        cp_async16(sbase + A_STAGE_BYTES + sw,
                   g_Bcat + (size_t)(n0 + row) * (size_t)K_EFF + bcol + j * 8);
    }
}

__global__ void __launch_bounds__(THREADS, 1) gemm_kernel(float* __restrict__ z) {
    extern __shared__ char smem[];
    const uint32_t sbase = smem_u32(smem);
    const int t    = threadIdx.x;
    const int wid  = t >> 5;
    const int lane = t & 31;

    const int n0 = blockIdx.x * BN;
    const int m0 = blockIdx.y * BM;

    const int warpM = wid >> 1;         // 0..3  (64 rows each)
    const int warpN = wid & 1;          // 0..1  (64 cols each)
    const int wm = warpM * 64;
    const int wn = warpN * 64;

    // ldmatrix lane geometry
    const int q = lane >> 3;            // matrix index 0..3
    const int r = lane & 7;             // row within 8x8 matrix

    float acc[4][8][4];                 // [m-tile][n-tile][frag]
    #pragma unroll
    for (int i = 0; i < 4; i++)
        #pragma unroll
        for (int j2 = 0; j2 < 8; j2++)
            #pragma unroll
            for (int c = 0; c < 4; c++) acc[i][j2][c] = 0.0f;

    // Prefetch stages 0,1
    load_stage(sbase + 0 * STAGE_BYTES, 0, m0, n0, t);
    cp_commit();
    load_stage(sbase + 1 * STAGE_BYTES, 1, m0, n0, t);
    cp_commit();

    for (int kt = 0; kt < NSTEPS; kt++) {
        if (kt + 2 < NSTEPS)
            load_stage(sbase + ((kt + 2) % STAGES) * STAGE_BYTES, kt + 2, m0, n0, t);
        cp_commit();
        cp_wait2();                      // stage kt resident
        __syncthreads();

        const uint32_t astg = sbase + (kt % STAGES) * STAGE_BYTES;
        const uint32_t bstg = astg + A_STAGE_BYTES;

        #pragma unroll
        for (int kk = 0; kk < BK / 16; kk++) {        // 4 k16 steps
            const uint32_t kb = kk * 32;              // byte offset of k16 block

            // A fragments: 4 m-tiles
            uint32_t a[4][4];
            #pragma unroll
            for (int mt = 0; mt < 4; mt++) {
                const int arow = wm + mt * 16 + ((q & 1) ? 8 : 0) + r;
                const uint32_t koff = kb + ((q >= 2) ? 16 : 0);
                const uint32_t addr = astg + sw128((uint32_t)arow * 128 + koff);
                ldmatrix_x4(a[mt][0], a[mt][1], a[mt][2], a[mt][3], addr);
            }
            // B fragments: 8 n-tiles (2 per ldmatrix.x4)
            uint32_t b[8][2];
            #pragma unroll
            for (int bt = 0; bt < 4; bt++) {
                const int brow = wn + bt * 16 + ((q >= 2) ? 8 : 0) + r;
                const uint32_t koff = kb + ((q & 1) ? 16 : 0);
                const uint32_t addr = bstg + sw128((uint32_t)brow * 128 + koff);
                uint32_t r0, r1, r2, r3;
                ldmatrix_x4(r0, r1, r2, r3, addr);
                b[bt * 2 + 0][0] = r0; b[bt * 2 + 0][1] = r1;
                b[bt * 2 + 1][0] = r2; b[bt * 2 + 1][1] = r3;
            }
            // 32 MMAs
            #pragma unroll
            for (int mt = 0; mt < 4; mt++)
                #pragma unroll
                for (int nt = 0; nt < 8; nt++)
                    mma_16816(acc[mt][nt][0], acc[mt][nt][1], acc[mt][nt][2], acc[mt][nt][3],
                              a[mt][0], a[mt][1], a[mt][2], a[mt][3],
                              b[nt][0], b[nt][1]);
        }
        __syncthreads();                 // protect stage kt%3 before iter kt+1 overwrites it
    }

    // Epilogue: c frag (m16n8): {c0,c1} at (row = t/4, col = (t%4)*2), {c2,c3} at row+8
    const int crow = lane >> 2;
    const int ccol = (lane & 3) * 2;
    #pragma unroll
    for (int mt = 0; mt < 4; mt++) {
        const int gm = m0 + wm + mt * 16 + crow;
        #pragma unroll
        for (int nt = 0; nt < 8; nt++) {
            const int gn = n0 + wn + nt * 8 + ccol;
            float* p0 = z + (size_t)gm * FEATURES + gn;
            float* p1 = z + (size_t)(gm + 8) * FEATURES + gn;
            *reinterpret_cast<float2*>(p0) = make_float2(acc[mt][nt][0], acc[mt][nt][1]);
            *reinterpret_cast<float2*>(p1) = make_float2(acc[mt][nt][2], acc[mt][nt][3]);
        }
    }
}

// ---------------------------------------------------------------------------
// Launch
// ---------------------------------------------------------------------------
extern "C" void kernel_launch(void* const* d_in, const int* in_sizes, int n_in,
                              void* d_out, int out_size) {
    (void)in_sizes; (void)n_in; (void)out_size;
    const float* x     = (const float*)d_in[0];   // [4096, 8, 1024]
    const float* scale = (const float*)d_in[1];   // [1024]
    const float* W     = (const float*)d_in[2];   // [1024, 1024]

    float* z  = (float*)d_out;                         // [32768, 1024]
    float* ln = z + (size_t)M_TOTAL * FEATURES;        // [32768, 1024]

    cudaFuncSetAttribute(gemm_kernel, cudaFuncAttributeMaxDynamicSharedMemorySize, SMEM_TOTAL);

    ln_kernel<<<M_TOTAL, 256>>>(x, scale, ln);
    pack_b_kernel<<<dim3(32, 32), dim3(32, 8)>>>(W);

    dim3 grid(FEATURES / BN, M_TOTAL / BM);            // (8, 128)
    gemm_kernel<<<grid, THREADS, SMEM_TOTAL>>>(z);
}